// round 2
// baseline (speedup 1.0000x reference)
#include <cuda_runtime.h>
#include <cstdint>

// ---------------- problem constants ----------------
#define NBATCH 4
#define NTIME  5
#define GXDIM  400
#define GYDIM  400
#define KTOT   (NBATCH * GXDIM * GYDIM * NTIME)   // 3,200,000 keys

// scan tiling: 3125 tiles * 1024 keys == KTOT exactly
#define SB     256
#define SI     4
#define STILE  (SB * SI)                          // 1024
#define NTILES (KTOT / STILE)                     // 3125

// ---------------- device scratch (no allocations allowed) ----------------
__device__ float4 d_acc[KTOT];       // [count, sum_x, sum_y, sum_z] per key
__device__ int    d_rank[KTOT];      // rank (unique index) per present key
__device__ int    d_partials[NTILES];

// ---------------- helpers ----------------
__device__ __forceinline__ int point_key(const float* __restrict__ p,
                                         int& cx, int& cy) {
    // matches reference f32 math: (v - pr)/vs, truncate (coords >= 0)
    float x = p[1], y = p[2];
    cx = (int)((x + 50.0f) / 0.25f);
    cy = (int)((y + 50.0f) / 0.25f);
    int b = (int)p[0];
    int t = (int)p[5];
    return ((b * GXDIM + cx) * GYDIM + cy) * NTIME + t;
}

// ---------------- kernels ----------------
__global__ void k_init(float* __restrict__ out, int N) {
    int tid = blockIdx.x * blockDim.x + threadIdx.x;
    int stride = gridDim.x * blockDim.x;
    const float4 z4 = make_float4(0.f, 0.f, 0.f, 0.f);
    for (int i = tid; i < KTOT; i += stride) d_acc[i] = z4;

    // unq region (4N floats at offset 9N) pre-filled with -1 (padding rows)
    float4* unq4 = reinterpret_cast<float4*>(out + (size_t)9 * N);
    const float4 m1 = make_float4(-1.f, -1.f, -1.f, -1.f);
    for (int i = tid; i < N; i += stride) unq4[i] = m1;

    if (tid == 0) {
        float* g = out + (size_t)14 * N;   // grid_size [400,400,1]
        g[0] = 400.0f; g[1] = 400.0f; g[2] = 1.0f;
    }
}

__global__ void k_accum(const float* __restrict__ pts, int N) {
    int i = blockIdx.x * blockDim.x + threadIdx.x;
    if (i >= N) return;
    const float* p = pts + (size_t)i * 6;
    int cx, cy;
    int key = point_key(p, cx, cy);
    float4* a = &d_acc[key];
    atomicAdd(&a->x, 1.0f);
    atomicAdd(&a->y, p[1]);
    atomicAdd(&a->z, p[2]);
    atomicAdd(&a->w, p[3]);
}

// per-tile count of present keys (order-free sum; coalesced strided reads)
__global__ void k_tile_sums() {
    int tile = blockIdx.x;
    int t = threadIdx.x;
    int base = tile * STILE;
    int s = 0;
#pragma unroll
    for (int j = 0; j < SI; j++) {
        int k = base + t + j * SB;
        s += (d_acc[k].x > 0.0f) ? 1 : 0;
    }
    __shared__ int sh[SB];
    sh[t] = s;
    __syncthreads();
    for (int off = SB / 2; off > 0; off >>= 1) {
        if (t < off) sh[t] += sh[t + off];
        __syncthreads();
    }
    if (t == 0) d_partials[tile] = sh[0];
}

// exclusive scan of the 3125 tile totals, single block
__global__ void k_scan_partials() {
    __shared__ int sh[1024];
    __shared__ int s_run;
    int t = threadIdx.x;
    if (t == 0) s_run = 0;
    __syncthreads();
    for (int base = 0; base < NTILES; base += 1024) {
        int idx = base + t;
        int v = (idx < NTILES) ? d_partials[idx] : 0;
        sh[t] = v;
        __syncthreads();
        // Hillis-Steele inclusive scan
        for (int off = 1; off < 1024; off <<= 1) {
            int u = (t >= off) ? sh[t - off] : 0;
            __syncthreads();
            sh[t] += u;
            __syncthreads();
        }
        int incl = sh[t];
        if (idx < NTILES) d_partials[idx] = incl - v + s_run;
        __syncthreads();
        if (t == 1023) s_run += incl;
        __syncthreads();
    }
}

// assign ranks (== sorted-unique index), decode + write unq rows
__global__ void k_rank_unq(float* __restrict__ out_unq) {
    int tile = blockIdx.x;
    int t = threadIdx.x;
    int base = tile * STILE + t * SI;   // blocked: keys handled in ascending order
    int f[SI];
    int s = 0;
#pragma unroll
    for (int j = 0; j < SI; j++) {
        f[j] = (d_acc[base + j].x > 0.0f) ? 1 : 0;
        s += f[j];
    }
    __shared__ int sh[SB];
    sh[t] = s;
    __syncthreads();
    for (int off = 1; off < SB; off <<= 1) {
        int u = (t >= off) ? sh[t - off] : 0;
        __syncthreads();
        sh[t] += u;
        __syncthreads();
    }
    int run = sh[t] - s + d_partials[tile];   // exclusive prefix, global
#pragma unroll
    for (int j = 0; j < SI; j++) {
        if (f[j]) {
            int k = base + j;
            d_rank[k] = run;
            int tt = k % NTIME;  int k2 = k / NTIME;
            int yy = k2 % GYDIM; k2 /= GYDIM;
            int xx = k2 % GXDIM;
            int bb = k2 / GXDIM;
            float4 row = make_float4((float)bb, (float)tt, (float)yy, (float)xx);
            reinterpret_cast<float4*>(out_unq)[run] = row;
            run++;
        }
    }
}

__global__ void k_feat(const float* __restrict__ pts, float* __restrict__ out, int N) {
    int i = blockIdx.x * blockDim.x + threadIdx.x;
    if (i >= N) return;
    const float* p = pts + (size_t)i * 6;
    float x = p[1], y = p[2], z = p[3], inten = p[4];
    int cx, cy;
    int key = point_key(p, cx, cy);
    float4 a = d_acc[key];
    float c = fmaxf(a.x, 1.0f);
    float mx = a.y / c, my = a.z / c, mz = a.w / c;
    float fcx = x - (((float)cx * 0.25f + 0.125f) + -50.0f);
    float fcy = y - (((float)cy * 0.25f + 0.125f) + -50.0f);

    float* f = out + (size_t)i * 9;
    f[0] = x;      f[1] = y;      f[2] = z;   f[3] = inten;
    f[4] = x - mx; f[5] = y - my; f[6] = z - mz;
    f[7] = fcx;    f[8] = fcy;

    out[(size_t)13 * N + i] = (float)d_rank[key];   // unq_inv
}

// ---------------- launch ----------------
extern "C" void kernel_launch(void* const* d_in, const int* in_sizes, int n_in,
                              void* d_out, int out_size) {
    const float* pts = (const float*)d_in[0];
    int N = in_sizes[0] / 6;
    float* out = (float*)d_out;

    k_init<<<1024, 256>>>(out, N);
    int nb = (N + 255) / 256;
    k_accum<<<nb, 256>>>(pts, N);
    k_tile_sums<<<NTILES, SB>>>();
    k_scan_partials<<<1, 1024>>>();
    k_rank_unq<<<NTILES, SB>>>(out + (size_t)9 * N);
    k_feat<<<nb, 256>>>(pts, out, N);
}

// round 5
// speedup vs baseline: 1.0619x; 1.0619x over previous
#include <cuda_runtime.h>
#include <cstdint>

// ---------------- problem constants ----------------
#define NBATCH 4
#define NTIME  5
#define GXDIM  400
#define GYDIM  400
#define KTOT   (NBATCH * GXDIM * GYDIM * NTIME)   // 3,200,000 keys

// lookback scan tiling: 625 tiles * 5120 keys == KTOT exactly
#define LB_T    256
#define LB_PK   20
#define LB_TILE (LB_T * LB_PK)                    // 5120
#define LB_NT   (KTOT / LB_TILE)                  // 625

// ---------------- device scratch (no allocations allowed) ----------------
__device__ float4       d_acc[KTOT];     // [count, sum_x, sum_y, sum_z] per key
__device__ int          d_rank[KTOT];    // rank (unique index) per present key
__device__ unsigned int d_state[LB_NT];  // lookback tile states: flag<<30 | value
__device__ int          d_tile_ctr;
__device__ int          d_nuniq;

// ---------------- helpers ----------------
__device__ __forceinline__ int point_key(const float* __restrict__ p,
                                         int& cx, int& cy) {
    float x = p[1], y = p[2];
    cx = (int)((x + 50.0f) / 0.25f);
    cy = (int)((y + 50.0f) / 0.25f);
    int b = (int)p[0];
    int t = (int)p[5];
    return ((b * GXDIM + cx) * GYDIM + cy) * NTIME + t;
}

// ---------------- kernels ----------------
__global__ void k_init(float* __restrict__ out, int N) {
    int tid = blockIdx.x * blockDim.x + threadIdx.x;
    int stride = gridDim.x * blockDim.x;
    const float4 z4 = make_float4(0.f, 0.f, 0.f, 0.f);
    for (int i = tid; i < KTOT; i += stride) d_acc[i] = z4;
    for (int i = tid; i < LB_NT; i += stride) d_state[i] = 0u;
    if (tid == 0) {
        d_tile_ctr = 0;
        d_nuniq = 0;
        float* g = out + (size_t)14 * N;   // grid_size [400,400,1]
        g[0] = 400.0f; g[1] = 400.0f; g[2] = 1.0f;
    }
}

__global__ void k_accum(const float* __restrict__ pts, int N) {
    int i = blockIdx.x * blockDim.x + threadIdx.x;
    if (i >= N) return;
    const float* p = pts + (size_t)i * 6;
    float x = p[1], y = p[2], z = p[3];
    int cx, cy;
    int key = point_key(p, cx, cy);
    // one vector reduction per point: {count, x, y, z}
    asm volatile("red.global.add.v4.f32 [%0], {%1, %2, %3, %4};"
                 :: "l"(&d_acc[key]), "f"(1.0f), "f"(x), "f"(y), "f"(z)
                 : "memory");
}

// fused presence-scan + rank assignment + unq decode (decoupled lookback)
__global__ void __launch_bounds__(LB_T)
k_scanrank(float* __restrict__ out_unq) {
    __shared__ int s_tile;
    __shared__ int s_wsum[LB_T / 32];
    __shared__ int s_base;

    if (threadIdx.x == 0) s_tile = atomicAdd(&d_tile_ctr, 1);
    __syncthreads();
    const int tile = s_tile;
    const int t = threadIdx.x;
    const int lane = t & 31, warp = t >> 5;
    const int base = tile * LB_TILE + t * LB_PK;   // blocked: ascending key order

    unsigned int flags = 0;
    int s = 0;
#pragma unroll
    for (int j = 0; j < LB_PK; j++) {
        int f = (d_acc[base + j].x > 0.0f) ? 1 : 0;
        flags |= (unsigned)f << j;
        s += f;
    }

    // warp inclusive scan of per-thread sums
    int incl = s;
#pragma unroll
    for (int o = 1; o < 32; o <<= 1) {
        int u = __shfl_up_sync(0xffffffffu, incl, o);
        if (lane >= o) incl += u;
    }
    if (lane == 31) s_wsum[warp] = incl;
    __syncthreads();
    if (warp == 0 && lane < (LB_T / 32)) {
        int v = s_wsum[lane];
        int iv = v;
#pragma unroll
        for (int o = 1; o < (LB_T / 32); o <<= 1) {
            int u = __shfl_up_sync(0xffu, iv, o);
            if (lane >= o) iv += u;
        }
        s_wsum[lane] = iv;   // inclusive warp prefix
    }
    __syncthreads();
    const int block_total = s_wsum[(LB_T / 32) - 1];
    const int thread_excl = ((warp == 0) ? 0 : s_wsum[warp - 1]) + (incl - s);

    // publish + lookback (thread 0)
    if (t == 0) {
        if (tile == 0) {
            atomicExch(&d_state[0], (2u << 30) | (unsigned)block_total);
            s_base = 0;
        } else {
            atomicExch(&d_state[tile], (1u << 30) | (unsigned)block_total);
            int excl = 0;
            int pt = tile - 1;
            while (true) {
                unsigned v = atomicAdd(&d_state[pt], 0u);
                unsigned fl = v >> 30;
                if (fl == 0u) continue;              // not yet published
                excl += (int)(v & 0x3FFFFFFFu);
                if (fl == 2u) break;                 // inclusive prefix found
                pt--;
            }
            atomicExch(&d_state[tile], (2u << 30) | (unsigned)(excl + block_total));
            s_base = excl;
        }
        if (tile == LB_NT - 1) {
            // total uniques = inclusive of last tile
            unsigned v = atomicAdd(&d_state[tile], 0u);
            d_nuniq = (int)(v & 0x3FFFFFFFu);
        }
    }
    __syncthreads();

    int run = s_base + thread_excl;
#pragma unroll
    for (int j = 0; j < LB_PK; j++) {
        if ((flags >> j) & 1u) {
            int k = base + j;
            d_rank[k] = run;
            int tt = k % NTIME;  int k2 = k / NTIME;
            int yy = k2 % GYDIM; k2 /= GYDIM;
            int xx = k2 % GXDIM;
            int bb = k2 / GXDIM;
            reinterpret_cast<float4*>(out_unq)[run] =
                make_float4((float)bb, (float)tt, (float)yy, (float)xx);
            run++;
        }
    }
}

// fill padded unq rows [n_unique, N) with -1
__global__ void k_pad(float* __restrict__ out_unq, int N) {
    int i = blockIdx.x * blockDim.x + threadIdx.x;
    if (i >= N) return;
    if (i >= d_nuniq)
        reinterpret_cast<float4*>(out_unq)[i] = make_float4(-1.f, -1.f, -1.f, -1.f);
}

__global__ void k_feat(const float* __restrict__ pts, float* __restrict__ out, int N) {
    int i = blockIdx.x * blockDim.x + threadIdx.x;
    if (i >= N) return;
    const float* p = pts + (size_t)i * 6;
    float x = p[1], y = p[2], z = p[3], inten = p[4];
    int cx, cy;
    int key = point_key(p, cx, cy);
    float4 a = d_acc[key];
    float c = fmaxf(a.x, 1.0f);
    float mx = a.y / c, my = a.z / c, mz = a.w / c;
    float fcx = x - (((float)cx * 0.25f + 0.125f) + -50.0f);
    float fcy = y - (((float)cy * 0.25f + 0.125f) + -50.0f);

    float* f = out + (size_t)i * 9;
    f[0] = x;      f[1] = y;      f[2] = z;   f[3] = inten;
    f[4] = x - mx; f[5] = y - my; f[6] = z - mz;
    f[7] = fcx;    f[8] = fcy;

    out[(size_t)13 * N + i] = (float)d_rank[key];   // unq_inv
}

// ---------------- launch ----------------
extern "C" void kernel_launch(void* const* d_in, const int* in_sizes, int n_in,
                              void* d_out, int out_size) {
    const float* pts = (const float*)d_in[0];
    int N = in_sizes[0] / 6;
    float* out = (float*)d_out;
    float* out_unq = out + (size_t)9 * N;

    k_init<<<2048, 256>>>(out, N);
    int nb = (N + 255) / 256;
    k_accum<<<nb, 256>>>(pts, N);
    k_scanrank<<<LB_NT, LB_T>>>(out_unq);
    k_pad<<<nb, 256>>>(out_unq, N);
    k_feat<<<nb, 256>>>(pts, out, N);
}

// round 13
// speedup vs baseline: 1.3602x; 1.2809x over previous
#include <cuda_runtime.h>
#include <cstdint>

// ---------------- problem constants ----------------
#define NBATCH 4
#define NTIME  5
#define GXDIM  400
#define GYDIM  400
#define KTOT   (NBATCH * GXDIM * GYDIM * NTIME)   // 3,200,000 keys

// lookback scan tiling: 625 tiles * 5120 keys == KTOT exactly
#define LB_T    256
#define LB_PK   20
#define LB_TILE (LB_T * LB_PK)                    // 5120
#define LB_NT   (KTOT / LB_TILE)                  // 625

// ---------------- device scratch (no allocations allowed) ----------------
__device__ float4       d_acc[KTOT];     // [count, sum_x, sum_y, sum_z] per key
__device__ int          d_rank[KTOT];    // rank (unique index) per present key
__device__ unsigned int d_state[LB_NT];  // lookback tile states: flag<<30 | value
__device__ int          d_tile_ctr;
__device__ int          d_nuniq;

// ---------------- helpers ----------------
__device__ __forceinline__ int point_key(const float* __restrict__ p,
                                         int& cx, int& cy) {
    float x = p[1], y = p[2];
    cx = (int)((x + 50.0f) / 0.25f);
    cy = (int)((y + 50.0f) / 0.25f);
    int b = (int)p[0];
    int t = (int)p[5];
    return ((b * GXDIM + cx) * GYDIM + cy) * NTIME + t;
}

// ---------------- kernels ----------------
__global__ void k_init(float* __restrict__ out, int N) {
    int tid = blockIdx.x * blockDim.x + threadIdx.x;
    int stride = gridDim.x * blockDim.x;
    const float4 z4 = make_float4(0.f, 0.f, 0.f, 0.f);
    for (int i = tid; i < KTOT; i += stride) d_acc[i] = z4;
    for (int i = tid; i < LB_NT; i += stride) d_state[i] = 0u;
    if (tid == 0) {
        d_tile_ctr = 0;
        d_nuniq = 0;
        float* g = out + (size_t)14 * N;   // grid_size [400,400,1]
        g[0] = 400.0f; g[1] = 400.0f; g[2] = 1.0f;
    }
}

__global__ void k_accum(const float* __restrict__ pts, int N) {
    int i = blockIdx.x * blockDim.x + threadIdx.x;
    if (i >= N) return;
    const float* p = pts + (size_t)i * 6;
    float x = p[1], y = p[2], z = p[3];
    int cx, cy;
    int key = point_key(p, cx, cy);
    // one vector reduction per point: {count, x, y, z}
    asm volatile("red.global.add.v4.f32 [%0], {%1, %2, %3, %4};"
                 :: "l"(&d_acc[key]), "f"(1.0f), "f"(x), "f"(y), "f"(z)
                 : "memory");
}

// fused presence-scan + rank assignment + unq decode (decoupled lookback)
__global__ void __launch_bounds__(LB_T)
k_scanrank(float* __restrict__ out_unq) {
    __shared__ int s_tile;
    __shared__ int s_wsum[LB_T / 32];
    __shared__ int s_base;

    if (threadIdx.x == 0) s_tile = atomicAdd(&d_tile_ctr, 1);
    __syncthreads();
    const int tile = s_tile;
    const int t = threadIdx.x;
    const int lane = t & 31, warp = t >> 5;
    const int base = tile * LB_TILE + t * LB_PK;   // blocked: ascending key order

    unsigned int flags = 0;
    int s = 0;
#pragma unroll
    for (int j = 0; j < LB_PK; j++) {
        int f = (d_acc[base + j].x > 0.0f) ? 1 : 0;
        flags |= (unsigned)f << j;
        s += f;
    }

    int incl = s;
#pragma unroll
    for (int o = 1; o < 32; o <<= 1) {
        int u = __shfl_up_sync(0xffffffffu, incl, o);
        if (lane >= o) incl += u;
    }
    if (lane == 31) s_wsum[warp] = incl;
    __syncthreads();
    if (warp == 0 && lane < (LB_T / 32)) {
        int v = s_wsum[lane];
        int iv = v;
#pragma unroll
        for (int o = 1; o < (LB_T / 32); o <<= 1) {
            int u = __shfl_up_sync(0xffu, iv, o);
            if (lane >= o) iv += u;
        }
        s_wsum[lane] = iv;
    }
    __syncthreads();
    const int block_total = s_wsum[(LB_T / 32) - 1];
    const int thread_excl = ((warp == 0) ? 0 : s_wsum[warp - 1]) + (incl - s);

    if (t == 0) {
        if (tile == 0) {
            atomicExch(&d_state[0], (2u << 30) | (unsigned)block_total);
            s_base = 0;
        } else {
            atomicExch(&d_state[tile], (1u << 30) | (unsigned)block_total);
            int excl = 0;
            int pt = tile - 1;
            while (true) {
                unsigned v = atomicAdd(&d_state[pt], 0u);
                unsigned fl = v >> 30;
                if (fl == 0u) continue;
                excl += (int)(v & 0x3FFFFFFFu);
                if (fl == 2u) break;
                pt--;
            }
            atomicExch(&d_state[tile], (2u << 30) | (unsigned)(excl + block_total));
            s_base = excl;
        }
        if (tile == LB_NT - 1) {
            unsigned v = atomicAdd(&d_state[tile], 0u);
            d_nuniq = (int)(v & 0x3FFFFFFFu);
        }
    }
    __syncthreads();

    int run = s_base + thread_excl;
#pragma unroll
    for (int j = 0; j < LB_PK; j++) {
        if ((flags >> j) & 1u) {
            int k = base + j;
            d_rank[k] = run;
            int tt = k % NTIME;  int k2 = k / NTIME;
            int yy = k2 % GYDIM; k2 /= GYDIM;
            int xx = k2 % GXDIM;
            int bb = k2 / GXDIM;
            reinterpret_cast<float4*>(out_unq)[run] =
                make_float4((float)bb, (float)tt, (float)yy, (float)xx);
            run++;
        }
    }
}

// fill padded unq rows [n_unique, N) with -1
__global__ void k_pad(float* __restrict__ out_unq, int N) {
    int i = blockIdx.x * blockDim.x + threadIdx.x;
    if (i >= N) return;
    if (i >= d_nuniq)
        reinterpret_cast<float4*>(out_unq)[i] = make_float4(-1.f, -1.f, -1.f, -1.f);
}

// features: 1 pt/thread, smem-staged coalesced output (ONLY change vs passing)
__global__ void __launch_bounds__(256)
k_feat(const float* __restrict__ pts, float* __restrict__ out, int N) {
    __shared__ __align__(16) float s[256 * 9];   // 9216 B
    const int tid = threadIdx.x;
    const int i = blockIdx.x * 256 + tid;
    const int base_pt = blockIdx.x * 256;

    if (i < N) {
        const float* p = pts + (size_t)i * 6;
        float x = p[1], y = p[2], z = p[3], inten = p[4];
        int cx, cy;
        int key = point_key(p, cx, cy);
        float4 a = d_acc[key];
        float c = fmaxf(a.x, 1.0f);
        float* r = s + tid * 9;
        r[0] = x;              r[1] = y;              r[2] = z;  r[3] = inten;
        r[4] = x - a.y / c;    r[5] = y - a.z / c;    r[6] = z - a.w / c;
        r[7] = x - (((float)cx * 0.25f + 0.125f) + -50.0f);
        r[8] = y - (((float)cy * 0.25f + 0.125f) + -50.0f);

        out[(size_t)13 * N + i] = (float)d_rank[key];   // unq_inv (scalar, as before)
    }
    __syncthreads();

    int cnt = N - base_pt; if (cnt > 256) cnt = 256;
    if (cnt == 256) {
        // full tile: 256*9 floats = 576 float4s, perfectly coalesced
        float4* dst = reinterpret_cast<float4*>(out + (size_t)base_pt * 9);
        const float4* src = reinterpret_cast<const float4*>(s);
#pragma unroll
        for (int j = 0; j < 576; j += 256) {
            int idx = j + tid;
            if (idx < 576) dst[idx] = src[idx];
        }
    } else if (cnt > 0) {
        int nf = cnt * 9;
        float* dst = out + (size_t)base_pt * 9;
        for (int j = tid; j < nf; j += 256) dst[j] = s[j];
    }
}

// ---------------- launch ----------------
extern "C" void kernel_launch(void* const* d_in, const int* in_sizes, int n_in,
                              void* d_out, int out_size) {
    const float* pts = (const float*)d_in[0];
    int N = in_sizes[0] / 6;
    float* out = (float*)d_out;
    float* out_unq = out + (size_t)9 * N;

    k_init<<<2048, 256>>>(out, N);
    int nb = (N + 255) / 256;
    k_accum<<<nb, 256>>>(pts, N);
    k_scanrank<<<LB_NT, LB_T>>>(out_unq);
    k_pad<<<nb, 256>>>(out_unq, N);
    k_feat<<<nb, 256>>>(pts, out, N);
}

// round 14
// speedup vs baseline: 1.3869x; 1.0196x over previous
#include <cuda_runtime.h>
#include <cstdint>

// ---------------- problem constants ----------------
#define NBATCH 4
#define NTIME  5
#define GXDIM  400
#define GYDIM  400
#define KTOT   (NBATCH * GXDIM * GYDIM * NTIME)   // 3,200,000 keys

// lookback scan tiling: 625 tiles * 5120 keys == KTOT exactly
#define LB_T    256
#define LB_PK   20
#define LB_TILE (LB_T * LB_PK)                    // 5120
#define LB_NT   (KTOT / LB_TILE)                  // 625

// ---------------- device scratch (no allocations allowed) ----------------
__device__ float4       d_acc[KTOT];     // [count, sum_x, sum_y, sum_z] per key
__device__ int          d_rank[KTOT];    // rank (unique index) per present key
__device__ unsigned int d_state[LB_NT];  // lookback tile states: flag<<30 | value
__device__ int          d_tile_ctr;
__device__ int          d_nuniq;

// ---------------- shared helpers ----------------
__device__ __forceinline__ int make_key(float bf, float x, float y, float tf,
                                        int& cx, int& cy) {
    cx = (int)((x + 50.0f) / 0.25f);
    cy = (int)((y + 50.0f) / 0.25f);
    return (((int)bf * GXDIM + cx) * GYDIM + cy) * NTIME + (int)tf;
}

__device__ __forceinline__ void accum_one(float bf, float x, float y, float z, float tf) {
    int cx, cy;
    int key = make_key(bf, x, y, tf, cx, cy);
    asm volatile("red.global.add.v4.f32 [%0], {%1, %2, %3, %4};"
                 :: "l"(&d_acc[key]), "f"(1.0f), "f"(x), "f"(y), "f"(z)
                 : "memory");
}

__device__ __forceinline__ float feat_one(float bf, float x, float y, float z,
                                          float inten, float tf, float* r) {
    int cx, cy;
    int key = make_key(bf, x, y, tf, cx, cy);
    float4 ac = d_acc[key];
    float c = fmaxf(ac.x, 1.0f);
    r[0] = x; r[1] = y; r[2] = z; r[3] = inten;
    r[4] = x - ac.y / c; r[5] = y - ac.z / c; r[6] = z - ac.w / c;
    r[7] = x - ((float)cx * 0.25f + 0.125f + -50.0f);
    r[8] = y - ((float)cy * 0.25f + 0.125f + -50.0f);
    return (float)d_rank[key];
}

// ---------------- kernels ----------------
__global__ void k_init(float* __restrict__ out, int N) {
    int tid = blockIdx.x * blockDim.x + threadIdx.x;
    int stride = gridDim.x * blockDim.x;
    const float4 z4 = make_float4(0.f, 0.f, 0.f, 0.f);
    for (int i = tid; i < KTOT; i += stride) d_acc[i] = z4;
    for (int i = tid; i < LB_NT; i += stride) d_state[i] = 0u;
    if (tid == 0) {
        d_tile_ctr = 0;
        d_nuniq = 0;
        float* g = out + (size_t)14 * N;   // grid_size [400,400,1]
        g[0] = 400.0f; g[1] = 400.0f; g[2] = 1.0f;
    }
}

// ---- accumulate: vectorized (16B-aligned pts), 2 pts/thread ----
__global__ void k_accum_v4(const float* __restrict__ pts, int N) {
    int t = blockIdx.x * blockDim.x + threadIdx.x;
    int i0 = t * 2;
    if (i0 >= N) return;
    const float4* p4 = reinterpret_cast<const float4*>(pts) + (size_t)t * 3;
    float4 a = p4[0];                       // p0: b, x, y, z
    float4 b = p4[1];                       // p0: inten, time ; p1: b, x
    accum_one(a.x, a.y, a.z, a.w, b.y);
    if (i0 + 1 < N) {
        float4 c = p4[2];                   // p1: y, z, inten, time
        accum_one(b.z, b.w, c.x, c.y, c.w);
    }
}

// ---- accumulate: scalar fallback ----
__global__ void k_accum_s(const float* __restrict__ pts, int N) {
    int t = blockIdx.x * blockDim.x + threadIdx.x;
    int i0 = t * 2;
    if (i0 >= N) return;
    const float* p = pts + (size_t)i0 * 6;
    accum_one(p[0], p[1], p[2], p[3], p[5]);
    if (i0 + 1 < N)
        accum_one(p[6], p[7], p[8], p[9], p[11]);
}

// fused presence-scan + rank assignment + unq decode (decoupled lookback)
__global__ void __launch_bounds__(LB_T)
k_scanrank(float* __restrict__ out_unq) {
    __shared__ int s_tile;
    __shared__ int s_wsum[LB_T / 32];
    __shared__ int s_base;

    if (threadIdx.x == 0) s_tile = atomicAdd(&d_tile_ctr, 1);
    __syncthreads();
    const int tile = s_tile;
    const int t = threadIdx.x;
    const int lane = t & 31, warp = t >> 5;
    const int base = tile * LB_TILE + t * LB_PK;   // blocked: ascending key order

    unsigned int flags = 0;
    int s = 0;
#pragma unroll
    for (int j = 0; j < LB_PK; j++) {
        int f = (d_acc[base + j].x > 0.0f) ? 1 : 0;
        flags |= (unsigned)f << j;
        s += f;
    }

    int incl = s;
#pragma unroll
    for (int o = 1; o < 32; o <<= 1) {
        int u = __shfl_up_sync(0xffffffffu, incl, o);
        if (lane >= o) incl += u;
    }
    if (lane == 31) s_wsum[warp] = incl;
    __syncthreads();
    if (warp == 0 && lane < (LB_T / 32)) {
        int v = s_wsum[lane];
        int iv = v;
#pragma unroll
        for (int o = 1; o < (LB_T / 32); o <<= 1) {
            int u = __shfl_up_sync(0xffu, iv, o);
            if (lane >= o) iv += u;
        }
        s_wsum[lane] = iv;
    }
    __syncthreads();
    const int block_total = s_wsum[(LB_T / 32) - 1];
    const int thread_excl = ((warp == 0) ? 0 : s_wsum[warp - 1]) + (incl - s);

    if (t == 0) {
        if (tile == 0) {
            atomicExch(&d_state[0], (2u << 30) | (unsigned)block_total);
            s_base = 0;
        } else {
            atomicExch(&d_state[tile], (1u << 30) | (unsigned)block_total);
            int excl = 0;
            int pt = tile - 1;
            while (true) {
                unsigned v = atomicAdd(&d_state[pt], 0u);
                unsigned fl = v >> 30;
                if (fl == 0u) continue;
                excl += (int)(v & 0x3FFFFFFFu);
                if (fl == 2u) break;
                pt--;
            }
            atomicExch(&d_state[tile], (2u << 30) | (unsigned)(excl + block_total));
            s_base = excl;
        }
        if (tile == LB_NT - 1) {
            unsigned v = atomicAdd(&d_state[tile], 0u);
            d_nuniq = (int)(v & 0x3FFFFFFFu);
        }
    }
    __syncthreads();

    int run = s_base + thread_excl;
#pragma unroll
    for (int j = 0; j < LB_PK; j++) {
        if ((flags >> j) & 1u) {
            int k = base + j;
            d_rank[k] = run;
            int tt = k % NTIME;  int k2 = k / NTIME;
            int yy = k2 % GYDIM; k2 /= GYDIM;
            int xx = k2 % GXDIM;
            int bb = k2 / GXDIM;
            reinterpret_cast<float4*>(out_unq)[run] =
                make_float4((float)bb, (float)tt, (float)yy, (float)xx);
            run++;
        }
    }
}

// shared tail: coalesced feature flush (GUARDED: 1152 % 256 != 0)
__device__ __forceinline__ void feat_tail(float* __restrict__ out, int N,
                                          const float* s, int base_pt, int tid) {
    __syncthreads();
    int cnt = N - base_pt; if (cnt > 512) cnt = 512;
    if (cnt == 512) {
        float4* dst = reinterpret_cast<float4*>(out + (size_t)base_pt * 9);
        const float4* src = reinterpret_cast<const float4*>(s);
#pragma unroll
        for (int j = 0; j < 1152; j += 256) {
            int idx = j + tid;
            if (idx < 1152) dst[idx] = src[idx];
        }
    } else if (cnt > 0) {
        int nf = cnt * 9;
        float* dst = out + (size_t)base_pt * 9;
        for (int j = tid; j < nf; j += 256) dst[j] = s[j];
    }
}

// ---- features: vectorized point loads, fused pad, 2 pts/thread ----
__global__ void __launch_bounds__(256)
k_feat_v4(const float* __restrict__ pts, float* __restrict__ out, int N) {
    __shared__ __align__(16) float s[512 * 9];   // 18432 B
    const int tid = threadIdx.x;
    const int t = blockIdx.x * 256 + tid;
    const int base_pt = blockIdx.x * 512;
    const int i0 = t * 2;
    const int nuniq = d_nuniq;

    if (i0 < N) {
        const float4* p4 = reinterpret_cast<const float4*>(pts) + (size_t)t * 3;
        float4 a = p4[0];                   // p0: b, x, y, z
        float4 b = p4[1];                   // p0: inten, time ; p1: b, x
        float2 inv;
        inv.x = feat_one(a.x, a.y, a.z, a.w, b.x, b.y, s + (tid * 2) * 9);
        if (i0 + 1 < N) {
            float4 c = p4[2];               // p1: y, z, inten, time
            inv.y = feat_one(b.z, b.w, c.x, c.y, c.z, c.w, s + (tid * 2 + 1) * 9);
            reinterpret_cast<float2*>(out + (size_t)13 * N)[t] = inv;
        } else {
            out[(size_t)13 * N + i0] = inv.x;
        }
        float4* unq4 = reinterpret_cast<float4*>(out + (size_t)9 * N);
        const float4 m1 = make_float4(-1.f, -1.f, -1.f, -1.f);
        if (i0 >= nuniq)                   unq4[i0] = m1;
        if (i0 + 1 < N && i0 + 1 >= nuniq) unq4[i0 + 1] = m1;
    }
    feat_tail(out, N, s, base_pt, tid);
}

// ---- features: scalar fallback ----
__global__ void __launch_bounds__(256)
k_feat_s(const float* __restrict__ pts, float* __restrict__ out, int N) {
    __shared__ __align__(16) float s[512 * 9];
    const int tid = threadIdx.x;
    const int t = blockIdx.x * 256 + tid;
    const int base_pt = blockIdx.x * 512;
    const int i0 = t * 2;
    const int nuniq = d_nuniq;

    if (i0 < N) {
        const float* p = pts + (size_t)i0 * 6;
        float2 inv;
        inv.x = feat_one(p[0], p[1], p[2], p[3], p[4], p[5], s + (tid * 2) * 9);
        if (i0 + 1 < N) {
            inv.y = feat_one(p[6], p[7], p[8], p[9], p[10], p[11],
                             s + (tid * 2 + 1) * 9);
            reinterpret_cast<float2*>(out + (size_t)13 * N)[t] = inv;
        } else {
            out[(size_t)13 * N + i0] = inv.x;
        }
        float4* unq4 = reinterpret_cast<float4*>(out + (size_t)9 * N);
        const float4 m1 = make_float4(-1.f, -1.f, -1.f, -1.f);
        if (i0 >= nuniq)                   unq4[i0] = m1;
        if (i0 + 1 < N && i0 + 1 >= nuniq) unq4[i0 + 1] = m1;
    }
    feat_tail(out, N, s, base_pt, tid);
}

// ---------------- launch ----------------
extern "C" void kernel_launch(void* const* d_in, const int* in_sizes, int n_in,
                              void* d_out, int out_size) {
    const float* pts = (const float*)d_in[0];
    int N = in_sizes[0] / 6;
    float* out = (float*)d_out;
    float* out_unq = out + (size_t)9 * N;

    int M = (N + 1) / 2;                     // threads handling 2 points each
    int nb2 = (M + 255) / 256;
    bool al16 = (((uintptr_t)pts) & 15u) == 0;   // fixed pointer -> deterministic

    k_init<<<2048, 256>>>(out, N);
    if (al16) k_accum_v4<<<nb2, 256>>>(pts, N);
    else      k_accum_s <<<nb2, 256>>>(pts, N);
    k_scanrank<<<LB_NT, LB_T>>>(out_unq);
    if (al16) k_feat_v4<<<nb2, 256>>>(pts, out, N);
    else      k_feat_s <<<nb2, 256>>>(pts, out, N);
}

// round 16
// speedup vs baseline: 1.5571x; 1.1227x over previous
#include <cuda_runtime.h>
#include <cstdint>

// ---------------- problem constants ----------------
#define NBATCH 4
#define NTIME  5
#define GXDIM  400
#define GYDIM  400
#define KTOT   (NBATCH * GXDIM * GYDIM * NTIME)   // 3,200,000 keys

// lookback scan tiling: 625 tiles * 5120 keys == KTOT exactly
#define LB_T    256
#define LB_PK   20
#define LB_TILE (LB_T * LB_PK)                    // 5120
#define LB_NT   (KTOT / LB_TILE)                  // 625

// ---------------- device scratch (no allocations allowed) ----------------
// Phase 1 (accum):   d_acc[key] = [count, sum_x, sum_y, sum_z]
// Phase 2 (scanrank) rewrites present keys in place:
//                    d_acc[key] = [mean_x, mean_y, mean_z, rank_as_float]
__device__ float4       d_acc[KTOT];
__device__ unsigned int d_state[LB_NT];  // lookback tile states: flag<<30 | value
__device__ int          d_tile_ctr;
__device__ int          d_nuniq;

// ---------------- shared helpers ----------------
__device__ __forceinline__ int make_key(float bf, float x, float y, float tf,
                                        int& cx, int& cy) {
    cx = (int)((x + 50.0f) / 0.25f);
    cy = (int)((y + 50.0f) / 0.25f);
    return (((int)bf * GXDIM + cx) * GYDIM + cy) * NTIME + (int)tf;
}

__device__ __forceinline__ void accum_one(float bf, float x, float y, float z, float tf) {
    int cx, cy;
    int key = make_key(bf, x, y, tf, cx, cy);
    asm volatile("red.global.add.v4.f32 [%0], {%1, %2, %3, %4};"
                 :: "l"(&d_acc[key]), "f"(1.0f), "f"(x), "f"(y), "f"(z)
                 : "memory");
}

// after scanrank: d_acc[key] = (mx, my, mz, rankf) — single gather per point
__device__ __forceinline__ float feat_one(float bf, float x, float y, float z,
                                          float inten, float tf, float* r) {
    int cx, cy;
    int key = make_key(bf, x, y, tf, cx, cy);
    float4 m = d_acc[key];
    r[0] = x; r[1] = y; r[2] = z; r[3] = inten;
    r[4] = x - m.x; r[5] = y - m.y; r[6] = z - m.z;
    r[7] = x - ((float)cx * 0.25f + 0.125f + -50.0f);
    r[8] = y - ((float)cy * 0.25f + 0.125f + -50.0f);
    return m.w;   // rank (exact integer in fp32)
}

// ---------------- kernels ----------------
__global__ void k_init(float* __restrict__ out, int N) {
    int tid = blockIdx.x * blockDim.x + threadIdx.x;
    int stride = gridDim.x * blockDim.x;
    const float4 z4 = make_float4(0.f, 0.f, 0.f, 0.f);
    for (int i = tid; i < KTOT; i += stride) d_acc[i] = z4;
    for (int i = tid; i < LB_NT; i += stride) d_state[i] = 0u;
    if (tid == 0) {
        d_tile_ctr = 0;
        d_nuniq = 0;
        float* g = out + (size_t)14 * N;   // grid_size [400,400,1]
        g[0] = 400.0f; g[1] = 400.0f; g[2] = 1.0f;
    }
}

// ---- accumulate: vectorized (16B-aligned pts), 2 pts/thread ----
__global__ void k_accum_v4(const float* __restrict__ pts, int N) {
    int t = blockIdx.x * blockDim.x + threadIdx.x;
    int i0 = t * 2;
    if (i0 >= N) return;
    const float4* p4 = reinterpret_cast<const float4*>(pts) + (size_t)t * 3;
    float4 a = p4[0];                       // p0: b, x, y, z
    float4 b = p4[1];                       // p0: inten, time ; p1: b, x
    accum_one(a.x, a.y, a.z, a.w, b.y);
    if (i0 + 1 < N) {
        float4 c = p4[2];                   // p1: y, z, inten, time
        accum_one(b.z, b.w, c.x, c.y, c.w);
    }
}

// ---- accumulate: scalar fallback ----
__global__ void k_accum_s(const float* __restrict__ pts, int N) {
    int t = blockIdx.x * blockDim.x + threadIdx.x;
    int i0 = t * 2;
    if (i0 >= N) return;
    const float* p = pts + (size_t)i0 * 6;
    accum_one(p[0], p[1], p[2], p[3], p[5]);
    if (i0 + 1 < N)
        accum_one(p[6], p[7], p[8], p[9], p[11]);
}

// fused presence-scan + rank + unq decode + IN-PLACE mean/rank rewrite
__global__ void __launch_bounds__(LB_T)
k_scanrank(float* __restrict__ out_unq) {
    __shared__ int s_tile;
    __shared__ int s_wsum[LB_T / 32];
    __shared__ int s_base;

    if (threadIdx.x == 0) s_tile = atomicAdd(&d_tile_ctr, 1);
    __syncthreads();
    const int tile = s_tile;
    const int t = threadIdx.x;
    const int lane = t & 31, warp = t >> 5;
    const int base = tile * LB_TILE + t * LB_PK;   // blocked: ascending key order

    unsigned int flags = 0;
    int s = 0;
#pragma unroll
    for (int j = 0; j < LB_PK; j++) {
        int f = (d_acc[base + j].x > 0.0f) ? 1 : 0;
        flags |= (unsigned)f << j;
        s += f;
    }

    int incl = s;
#pragma unroll
    for (int o = 1; o < 32; o <<= 1) {
        int u = __shfl_up_sync(0xffffffffu, incl, o);
        if (lane >= o) incl += u;
    }
    if (lane == 31) s_wsum[warp] = incl;
    __syncthreads();
    if (warp == 0 && lane < (LB_T / 32)) {
        int v = s_wsum[lane];
        int iv = v;
#pragma unroll
        for (int o = 1; o < (LB_T / 32); o <<= 1) {
            int u = __shfl_up_sync(0xffu, iv, o);
            if (lane >= o) iv += u;
        }
        s_wsum[lane] = iv;
    }
    __syncthreads();
    const int block_total = s_wsum[(LB_T / 32) - 1];
    const int thread_excl = ((warp == 0) ? 0 : s_wsum[warp - 1]) + (incl - s);

    if (t == 0) {
        if (tile == 0) {
            atomicExch(&d_state[0], (2u << 30) | (unsigned)block_total);
            s_base = 0;
        } else {
            atomicExch(&d_state[tile], (1u << 30) | (unsigned)block_total);
            int excl = 0;
            int pt = tile - 1;
            while (true) {
                unsigned v = atomicAdd(&d_state[pt], 0u);
                unsigned fl = v >> 30;
                if (fl == 0u) continue;
                excl += (int)(v & 0x3FFFFFFFu);
                if (fl == 2u) break;
                pt--;
            }
            atomicExch(&d_state[tile], (2u << 30) | (unsigned)(excl + block_total));
            s_base = excl;
        }
        if (tile == LB_NT - 1) {
            unsigned v = atomicAdd(&d_state[tile], 0u);
            d_nuniq = (int)(v & 0x3FFFFFFFu);
        }
    }
    __syncthreads();

    int run = s_base + thread_excl;
#pragma unroll
    for (int j = 0; j < LB_PK; j++) {
        if ((flags >> j) & 1u) {
            int k = base + j;
            // in-place: sums -> (mean, rank)
            float4 v = d_acc[k];
            float rc = 1.0f / v.x;          // count >= 1 for present keys
            d_acc[k] = make_float4(v.y * rc, v.z * rc, v.w * rc, (float)run);

            int tt = k % NTIME;  int k2 = k / NTIME;
            int yy = k2 % GYDIM; k2 /= GYDIM;
            int xx = k2 % GXDIM;
            int bb = k2 / GXDIM;
            reinterpret_cast<float4*>(out_unq)[run] =
                make_float4((float)bb, (float)tt, (float)yy, (float)xx);
            run++;
        }
    }
}

// shared tail: coalesced feature flush (GUARDED: 1152 % 256 != 0)
__device__ __forceinline__ void feat_tail(float* __restrict__ out, int N,
                                          const float* s, int base_pt, int tid) {
    __syncthreads();
    int cnt = N - base_pt; if (cnt > 512) cnt = 512;
    if (cnt == 512) {
        float4* dst = reinterpret_cast<float4*>(out + (size_t)base_pt * 9);
        const float4* src = reinterpret_cast<const float4*>(s);
#pragma unroll
        for (int j = 0; j < 1152; j += 256) {
            int idx = j + tid;
            if (idx < 1152) dst[idx] = src[idx];
        }
    } else if (cnt > 0) {
        int nf = cnt * 9;
        float* dst = out + (size_t)base_pt * 9;
        for (int j = tid; j < nf; j += 256) dst[j] = s[j];
    }
}

// ---- features: vectorized point loads, fused pad, 2 pts/thread ----
__global__ void __launch_bounds__(256)
k_feat_v4(const float* __restrict__ pts, float* __restrict__ out, int N) {
    __shared__ __align__(16) float s[512 * 9];   // 18432 B
    const int tid = threadIdx.x;
    const int t = blockIdx.x * 256 + tid;
    const int base_pt = blockIdx.x * 512;
    const int i0 = t * 2;
    const int nuniq = d_nuniq;

    if (i0 < N) {
        const float4* p4 = reinterpret_cast<const float4*>(pts) + (size_t)t * 3;
        float4 a = p4[0];                   // p0: b, x, y, z
        float4 b = p4[1];                   // p0: inten, time ; p1: b, x
        float2 inv;
        inv.x = feat_one(a.x, a.y, a.z, a.w, b.x, b.y, s + (tid * 2) * 9);
        if (i0 + 1 < N) {
            float4 c = p4[2];               // p1: y, z, inten, time
            inv.y = feat_one(b.z, b.w, c.x, c.y, c.z, c.w, s + (tid * 2 + 1) * 9);
            reinterpret_cast<float2*>(out + (size_t)13 * N)[t] = inv;
        } else {
            out[(size_t)13 * N + i0] = inv.x;
        }
        float4* unq4 = reinterpret_cast<float4*>(out + (size_t)9 * N);
        const float4 m1 = make_float4(-1.f, -1.f, -1.f, -1.f);
        if (i0 >= nuniq)                   unq4[i0] = m1;
        if (i0 + 1 < N && i0 + 1 >= nuniq) unq4[i0 + 1] = m1;
    }
    feat_tail(out, N, s, base_pt, tid);
}

// ---- features: scalar fallback ----
__global__ void __launch_bounds__(256)
k_feat_s(const float* __restrict__ pts, float* __restrict__ out, int N) {
    __shared__ __align__(16) float s[512 * 9];
    const int tid = threadIdx.x;
    const int t = blockIdx.x * 256 + tid;
    const int base_pt = blockIdx.x * 512;
    const int i0 = t * 2;
    const int nuniq = d_nuniq;

    if (i0 < N) {
        const float* p = pts + (size_t)i0 * 6;
        float2 inv;
        inv.x = feat_one(p[0], p[1], p[2], p[3], p[4], p[5], s + (tid * 2) * 9);
        if (i0 + 1 < N) {
            inv.y = feat_one(p[6], p[7], p[8], p[9], p[10], p[11],
                             s + (tid * 2 + 1) * 9);
            reinterpret_cast<float2*>(out + (size_t)13 * N)[t] = inv;
        } else {
            out[(size_t)13 * N + i0] = inv.x;
        }
        float4* unq4 = reinterpret_cast<float4*>(out + (size_t)9 * N);
        const float4 m1 = make_float4(-1.f, -1.f, -1.f, -1.f);
        if (i0 >= nuniq)                   unq4[i0] = m1;
        if (i0 + 1 < N && i0 + 1 >= nuniq) unq4[i0 + 1] = m1;
    }
    feat_tail(out, N, s, base_pt, tid);
}

// ---------------- launch ----------------
extern "C" void kernel_launch(void* const* d_in, const int* in_sizes, int n_in,
                              void* d_out, int out_size) {
    const float* pts = (const float*)d_in[0];
    int N = in_sizes[0] / 6;
    float* out = (float*)d_out;
    float* out_unq = out + (size_t)9 * N;

    int M = (N + 1) / 2;                     // threads handling 2 points each
    int nb2 = (M + 255) / 256;
    bool al16 = (((uintptr_t)pts) & 15u) == 0;   // fixed pointer -> deterministic

    k_init<<<2048, 256>>>(out, N);
    if (al16) k_accum_v4<<<nb2, 256>>>(pts, N);
    else      k_accum_s <<<nb2, 256>>>(pts, N);
    k_scanrank<<<LB_NT, LB_T>>>(out_unq);
    if (al16) k_feat_v4<<<nb2, 256>>>(pts, out, N);
    else      k_feat_s <<<nb2, 256>>>(pts, out, N);
}